// round 3
// baseline (speedup 1.0000x reference)
#include <cuda_runtime.h>
#include <cstddef>

#define NB   1024
#define NC   8
#define NT   32
#define NE   128
#define NH   256
#define SEG  64
#define SIG  1056

// ---------------- device scratch (no allocations allowed) ----------------
__device__ __align__(16) float g_W1t[NE * NH];    // [k][j]  transposed W1
__device__ __align__(16) float g_W2T[NH * SEG];   // [h][s]  (Winv @ W2)^T
__device__ __align__(16) float g_b2i[SEG];        // binv + Winv @ b2

// ---------------- prep kernels (run inside the graph every replay) -------
__global__ void prep_w1(const float* __restrict__ W1) {
    int id = blockIdx.x * 256 + threadIdx.x;      // 128 blocks * 256 = 32768
    int j = id >> 7;
    int k = id & 127;
    g_W1t[k * NH + j] = W1[id];                   // W1[j][k] -> W1t[k][j]
}

__global__ void prep_w2(const float* __restrict__ W2, const float* __restrict__ Winv,
                        const float* __restrict__ b2, const float* __restrict__ binv) {
    int s = blockIdx.x;        // 64
    int h = threadIdx.x;       // 256
    const float* wr = Winv + s * NE;
    float acc = 0.f;
    #pragma unroll 4
    for (int e = 0; e < NE; ++e) acc += wr[e] * W2[e * NH + h];
    g_W2T[h * SEG + s] = acc;
    if (h == 0) {
        float t = 0.f;
        for (int e = 0; e < NE; ++e) t += wr[e] * b2[e];
        g_b2i[s] = binv[s] + t;
    }
}

// ---------------- main kernel: one block per batch element ----------------
// smem layout (float offsets)
#define OFF_W1   0          // 32768  W1t [128][256]
#define OFF_W2C  32768      // 4096   W2inv chunk [64 k'][64 s]
#define OFF_ENC  36864      // 4096   enc tile [32][128]
#define OFF_H    40960      // 8192   h [32][256]
#define OFF_SIG  49152      // 1060   sig (index p+1, padded zeros at both ends)
#define OFF_OAC  50212      // 1056   conv accumulator
#define OFF_B1   51268      // 256
#define OFF_B2   51524      // 64
#define OFF_WCV  51588      // 28     conv weights
#define SMEM_FLOATS 51616
#define SMEM_BYTES  (SMEM_FLOATS * 4)

__device__ __forceinline__ float cinvf(int p) {
    return (p < 32 || p >= 1024) ? 1.0f : 0.5f;   // 1/overlap-count
}

__global__ __launch_bounds__(256, 1)
void decoder_main(const float* __restrict__ enc, const float* __restrict__ b1,
                  const float* __restrict__ Wconv, const float* __restrict__ bconv,
                  float* __restrict__ out) {
    extern __shared__ float sm[];
    float* W1s  = sm + OFF_W1;
    float* W2c  = sm + OFF_W2C;
    float* encS = sm + OFF_ENC;
    float* hS   = sm + OFF_H;
    float* sig  = sm + OFF_SIG;
    float* oac  = sm + OFF_OAC;
    float* b1s  = sm + OFF_B1;
    float* b2s  = sm + OFF_B2;
    float* wcv  = sm + OFF_WCV;

    const int tid = threadIdx.x;
    const int tj  = tid & 31;     // lane: covers j = jj*32+tj / s = ss*32+tj
    const int tt  = tid >> 5;     // warp: rows t = tt*4 + i
    const int b   = blockIdx.x;

    // ---- stage W1t (128 KB) once per block; small constants; zero oacc ----
    {
        const float4* src = (const float4*)g_W1t;
        float4*       dst = (float4*)W1s;
        #pragma unroll
        for (int r = 0; r < 32; ++r) dst[tid + 256 * r] = src[tid + 256 * r];
    }
    b1s[tid] = b1[tid];
    if (tid < SEG) b2s[tid] = g_b2i[tid];
    if (tid < 24)  wcv[tid] = Wconv[tid];
    for (int p = tid; p < SIG; p += 256) oac[p] = 0.f;
    __syncthreads();

    for (int c = 0; c < NC; ++c) {
        // ---- stage enc tile (16 KB), zero sig ----
        {
            const float4* src = (const float4*)(enc + (size_t)(b * NC + c) * (NT * NE));
            float4*       dst = (float4*)encS;
            #pragma unroll
            for (int r = 0; r < 4; ++r) dst[tid + 256 * r] = src[tid + 256 * r];
        }
        for (int p = tid; p < 1060; p += 256) sig[p] = 0.f;
        __syncthreads();

        // ---- GEMM1: h[32][256] = relu(enc @ W1^T + b1). tile 4t x 8j ----
        float acc[4][8];
        #pragma unroll
        for (int jj = 0; jj < 8; ++jj) {
            float bb = b1s[jj * 32 + tj];
            #pragma unroll
            for (int i = 0; i < 4; ++i) acc[i][jj] = bb;
        }
        {
            const float* e0 = encS + (tt * 4) * NE;
            #pragma unroll 2
            for (int k = 0; k < NE; k += 4) {
                float4 a0 = *(const float4*)(e0 + 0 * NE + k);
                float4 a1 = *(const float4*)(e0 + 1 * NE + k);
                float4 a2 = *(const float4*)(e0 + 2 * NE + k);
                float4 a3 = *(const float4*)(e0 + 3 * NE + k);
                #pragma unroll
                for (int kk = 0; kk < 4; ++kk) {
                    float av0 = ((const float*)&a0)[kk];
                    float av1 = ((const float*)&a1)[kk];
                    float av2 = ((const float*)&a2)[kk];
                    float av3 = ((const float*)&a3)[kk];
                    const float* wr = W1s + (k + kk) * NH + tj;
                    #pragma unroll
                    for (int jj = 0; jj < 8; ++jj) {
                        float w = wr[jj * 32];
                        acc[0][jj] += av0 * w;
                        acc[1][jj] += av1 * w;
                        acc[2][jj] += av2 * w;
                        acc[3][jj] += av3 * w;
                    }
                }
            }
        }
        #pragma unroll
        for (int i = 0; i < 4; ++i)
            #pragma unroll
            for (int jj = 0; jj < 8; ++jj)
                hS[(tt * 4 + i) * NH + jj * 32 + tj] = fmaxf(acc[i][jj], 0.f);
        __syncthreads();

        // ---- GEMM2 (folded): seg[32][64] = h @ W2inv^T + b2inv. tile 4t x 2s ----
        float sacc[4][2];
        #pragma unroll
        for (int ss = 0; ss < 2; ++ss) {
            float bb = b2s[ss * 32 + tj];
            #pragma unroll
            for (int i = 0; i < 4; ++i) sacc[i][ss] = bb;
        }
        for (int ch = 0; ch < 4; ++ch) {
            __syncthreads();   // previous chunk consumed (and hS ready on ch=0)
            {
                const float4* src = (const float4*)g_W2T + ch * 1024;
                float4*       dst = (float4*)W2c;
                #pragma unroll
                for (int r = 0; r < 4; ++r) dst[tid + 256 * r] = src[tid + 256 * r];
            }
            __syncthreads();
            const float* h0 = hS + (tt * 4) * NH + ch * 64;
            #pragma unroll 2
            for (int k = 0; k < 64; k += 4) {
                float4 a0 = *(const float4*)(h0 + 0 * NH + k);
                float4 a1 = *(const float4*)(h0 + 1 * NH + k);
                float4 a2 = *(const float4*)(h0 + 2 * NH + k);
                float4 a3 = *(const float4*)(h0 + 3 * NH + k);
                #pragma unroll
                for (int kk = 0; kk < 4; ++kk) {
                    const float* wr = W2c + (k + kk) * 64 + tj;
                    float w0 = wr[0];
                    float w1 = wr[32];
                    float av0 = ((const float*)&a0)[kk];
                    float av1 = ((const float*)&a1)[kk];
                    float av2 = ((const float*)&a2)[kk];
                    float av3 = ((const float*)&a3)[kk];
                    sacc[0][0] += av0 * w0;  sacc[0][1] += av0 * w1;
                    sacc[1][0] += av1 * w0;  sacc[1][1] += av1 * w1;
                    sacc[2][0] += av2 * w0;  sacc[2][1] += av2 * w1;
                    sacc[3][0] += av3 * w0;  sacc[3][1] += av3 * w1;
                }
            }
        }

        // ---- overlap-add into sig (<=2-way collisions, smem atomics) ----
        #pragma unroll
        for (int i = 0; i < 4; ++i)
            #pragma unroll
            for (int ss = 0; ss < 2; ++ss)
                atomicAdd(&sig[1 + (tt * 4 + i) * 32 + ss * 32 + tj], sacc[i][ss]);
        __syncthreads();

        // ---- normalize + conv tap for this channel, accumulate into oac ----
        {
            float w0c = wcv[c * 3 + 0];
            float w1c = wcv[c * 3 + 1];
            float w2c = wcv[c * 3 + 2];
            for (int p = tid; p < SIG; p += 256) {
                float vm = sig[p]     * cinvf(p - 1);   // sig[0]/sig[1057] are 0 pads
                float v0 = sig[p + 1] * cinvf(p);
                float vp = sig[p + 2] * cinvf(p + 1);
                oac[p] += w0c * vm + w1c * v0 + w2c * vp;
            }
        }
        __syncthreads();   // protect sig/encS before next channel restages
    }

    float bc = bconv[0];
    for (int p = tid; p < SIG; p += 256)
        out[(size_t)b * SIG + p] = oac[p] + bc;
}

// ---------------- launch ----------------
extern "C" void kernel_launch(void* const* d_in, const int* in_sizes, int n_in,
                              void* d_out, int out_size) {
    (void)in_sizes; (void)n_in; (void)out_size;
    const float* enc   = (const float*)d_in[0];
    const float* W1    = (const float*)d_in[1];
    const float* b1    = (const float*)d_in[2];
    const float* W2    = (const float*)d_in[3];
    const float* b2    = (const float*)d_in[4];
    const float* Winv  = (const float*)d_in[5];
    const float* binv  = (const float*)d_in[6];
    const float* Wconv = (const float*)d_in[7];
    const float* bconv = (const float*)d_in[8];
    float* out = (float*)d_out;

    cudaFuncSetAttribute(decoder_main, cudaFuncAttributeMaxDynamicSharedMemorySize,
                         SMEM_BYTES);

    prep_w1<<<128, 256>>>(W1);
    prep_w2<<<64, 256>>>(W2, Winv, b2, binv);
    decoder_main<<<NB, 256, SMEM_BYTES>>>(enc, b1, Wconv, bconv, out);
}

// round 4
// speedup vs baseline: 2.4718x; 2.4718x over previous
#include <cuda_runtime.h>
#include <cstdint>
#include <cstddef>

#define NB   1024
#define NC   8
#define NT   32
#define NE   128
#define NH   256
#define SEG  64
#define SIG  1056

// ---------------- device scratch (static; no allocations) ----------------
__device__ __align__(16) float g_W1p[8 * 16 * 32 * 8];       // 32768 tf32 patterns, frag-packed
__device__ __align__(16) float g_W2T[NH * SEG];              // [h][s] = (Winv@W2)^T
__device__ __align__(16) float g_W2p[2 * 8 * 16 * 32 * 2];   // 16384 tf32 patterns, frag-packed
__device__ __align__(16) float g_b2i[SEG];                   // binv + Winv@b2

// ---------------- helpers ----------------
__device__ __forceinline__ uint32_t f2tf32(float x) {
    uint32_t u;
    asm("cvt.rna.tf32.f32 %0, %1;" : "=r"(u) : "f"(x));
    return u;
}

#define MMA_TF32(C, A, b0v, b1v)                                               \
    asm volatile(                                                              \
        "mma.sync.aligned.m16n8k8.row.col.f32.tf32.tf32.f32 "                  \
        "{%0,%1,%2,%3},{%4,%5,%6,%7},{%8,%9},{%0,%1,%2,%3};"                   \
        : "+f"((C)[0]), "+f"((C)[1]), "+f"((C)[2]), "+f"((C)[3])               \
        : "r"((A)[0]), "r"((A)[1]), "r"((A)[2]), "r"((A)[3]),                  \
          "r"(b0v), "r"(b1v))

// ---------------- prep kernels ----------------
// W1 [j=256][k=128] -> fragment-packed tf32:
// g_W1p[((w*16+ks)*32+l)*8 + v]; v = nt*2+hh; value = W1[32w+8nt+g][8ks+tg+4hh]
__global__ void prep_w1p(const float* __restrict__ W1) {
    int id = blockIdx.x * 256 + threadIdx.x;     // 32768
    int v  = id & 7;
    int l  = (id >> 3) & 31;
    int ks = (id >> 8) & 15;
    int w  = id >> 12;
    int g = l >> 2, tg = l & 3, nt = v >> 1, hh = v & 1;
    int j = 32 * w + 8 * nt + g;
    int k = 8 * ks + tg + 4 * hh;
    ((uint32_t*)g_W1p)[id] = f2tf32(W1[j * NE + k]);
}

// W2T[h][s] = sum_e Winv[s][e]*W2[e][h];  b2i[s] = binv[s] + Winv[s]·b2
__global__ void prep_w2(const float* __restrict__ W2, const float* __restrict__ Winv,
                        const float* __restrict__ b2, const float* __restrict__ binv) {
    int s = blockIdx.x;        // 64
    int h = threadIdx.x;       // 256
    const float* wr = Winv + s * NE;
    float acc = 0.f;
    #pragma unroll 4
    for (int e = 0; e < NE; ++e) acc += wr[e] * W2[e * NH + h];
    g_W2T[h * SEG + s] = acc;
    if (h == 0) {
        float t = 0.f;
        for (int e = 0; e < NE; ++e) t += wr[e] * b2[e];
        g_b2i[s] = binv[s] + t;
    }
}

// W2T -> fragment-packed tf32 halves:
// g_W2p[((((half*8+w)*16+ksl)*32+l)*2)+hh]; value = W2T[8*(half*16+ksl)+tg+4hh][8w+g]
__global__ void prep_w2p() {
    int id  = blockIdx.x * 256 + threadIdx.x;    // 16384
    int hh  = id & 1;
    int l   = (id >> 1) & 31;
    int ksl = (id >> 6) & 15;
    int w   = (id >> 10) & 7;
    int hf  = id >> 13;
    int g = l >> 2, tg = l & 3;
    int kr = 8 * (hf * 16 + ksl) + tg + 4 * hh;  // h-row of W2T (0..255)
    int s  = 8 * w + g;
    ((uint32_t*)g_W2p)[id] = f2tf32(g_W2T[kr * SEG + s]);
}

// ---------------- main kernel ----------------
// smem float offsets
#define OFF_W1   0        // 32768  frag-packed W1 (tf32 bits)
#define OFF_W2C  32768    // 8192   one W2 half (tf32 bits)
#define OFF_ENC  40960    // 4224   enc tile [32][132] (tf32 bits, padded)
#define OFF_HA   45184    // 8192   h in GEMM2-A fragment order (tf32 bits)
#define OFF_SIG  53376    // 1058
#define OFF_OAC  54434    // 1056
#define OFF_B1   55490    // 256
#define OFF_B2   55746    // 64
#define OFF_WCV  55810    // 24
#define SMEM_FLOATS 55840
#define SMEM_BYTES  (SMEM_FLOATS * 4)

__device__ __forceinline__ float cinvf(int p) {
    return (p < 32 || p >= 1024) ? 1.0f : 0.5f;   // 1/overlap-count
}

__global__ __launch_bounds__(256, 1)
void decoder_main(const float* __restrict__ enc, const float* __restrict__ b1,
                  const float* __restrict__ Wconv, const float* __restrict__ bconv,
                  float* __restrict__ out) {
    extern __shared__ float sm[];
    float*    W1s  = sm + OFF_W1;
    float*    W2c  = sm + OFF_W2C;
    uint32_t* encU = (uint32_t*)(sm + OFF_ENC);
    uint32_t* hAU  = (uint32_t*)(sm + OFF_HA);
    float*    sig  = sm + OFF_SIG;
    float*    oac  = sm + OFF_OAC;
    float*    b1s  = sm + OFF_B1;
    float*    b2s  = sm + OFF_B2;
    float*    wcv  = sm + OFF_WCV;

    const int tid = threadIdx.x;
    const int l   = tid & 31;
    const int w   = tid >> 5;       // warp 0..7
    const int g   = l >> 2;
    const int tg  = l & 3;
    const int b   = blockIdx.x;

    // ---- one-time staging: W1p (128 KB), W2 half0 (32 KB), constants ----
    {
        const float4* src = (const float4*)g_W1p;
        float4*       dst = (float4*)W1s;
        #pragma unroll
        for (int r = 0; r < 32; ++r) dst[tid + 256 * r] = src[tid + 256 * r];
    }
    {
        const float4* src = (const float4*)g_W2p;
        float4*       dst = (float4*)W2c;
        #pragma unroll
        for (int r = 0; r < 8; ++r) dst[tid + 256 * r] = src[tid + 256 * r];
    }
    b1s[tid] = b1[tid];
    if (tid < SEG) b2s[tid] = g_b2i[tid];
    if (tid < 24)  wcv[tid] = Wconv[tid];
    for (int p = tid; p < SIG; p += 256) oac[p] = 0.f;
    __syncthreads();

    int cur = 0;   // W2 half currently resident in W2c

    for (int c = 0; c < NC; ++c) {
        // ---- stage enc tile -> tf32, padded stride 132; zero sig ----
        {
            const float4* src = (const float4*)(enc + (size_t)(b * NC + c) * (NT * NE));
            #pragma unroll
            for (int r = 0; r < 4; ++r) {
                int fi = tid + 256 * r;            // float4 index (0..1023)
                float4 v = src[fi];
                int m = fi >> 5, kq = fi & 31;
                uint4 u;
                u.x = f2tf32(v.x); u.y = f2tf32(v.y);
                u.z = f2tf32(v.z); u.w = f2tf32(v.w);
                *(uint4*)(encU + m * 132 + kq * 4) = u;
            }
        }
        for (int p = tid; p < 1058; p += 256) sig[p] = 0.f;
        __syncthreads();

        // ---- GEMM1: h[32][256] = enc @ W1^T (+b1), warp w -> j in [32w,32w+32) ----
        float c1[2][4][4];
        #pragma unroll
        for (int nt = 0; nt < 4; ++nt) {
            float bb0 = b1s[32 * w + 8 * nt + 2 * tg];
            float bb1 = b1s[32 * w + 8 * nt + 2 * tg + 1];
            #pragma unroll
            for (int mt = 0; mt < 2; ++mt) {
                c1[mt][nt][0] = bb0; c1[mt][nt][1] = bb1;
                c1[mt][nt][2] = bb0; c1[mt][nt][3] = bb1;
            }
        }
        #pragma unroll
        for (int ks = 0; ks < 16; ++ks) {
            uint32_t a[2][4];
            #pragma unroll
            for (int mt = 0; mt < 2; ++mt) {
                int r0 = (mt * 16 + g) * 132;
                int r1 = (mt * 16 + g + 8) * 132;
                int k0 = 8 * ks + tg;
                a[mt][0] = encU[r0 + k0];
                a[mt][1] = encU[r1 + k0];
                a[mt][2] = encU[r0 + k0 + 4];
                a[mt][3] = encU[r1 + k0 + 4];
            }
            uint4 B0 = ((const uint4*)W1s)[((w * 16 + ks) * 32 + l) * 2 + 0];
            uint4 B1 = ((const uint4*)W1s)[((w * 16 + ks) * 32 + l) * 2 + 1];
            #pragma unroll
            for (int mt = 0; mt < 2; ++mt) {
                MMA_TF32(c1[mt][0], a[mt], B0.x, B0.y);
                MMA_TF32(c1[mt][1], a[mt], B0.z, B0.w);
                MMA_TF32(c1[mt][2], a[mt], B1.x, B1.y);
                MMA_TF32(c1[mt][3], a[mt], B1.z, B1.w);
            }
        }

        // ---- epilogue: ReLU + tf32 + scatter into GEMM2-A fragment order ----
        {
            int col0 = 2 * tg, col1 = 2 * tg + 1;
            int i00 = (4 * g + (col0 & 3)) * 4 + 2 * (col0 >= 4);  // row g,  col0
            int i01 = (4 * g + (col1 & 3)) * 4 + 2 * (col1 >= 4);  // row g,  col1
            #pragma unroll
            for (int mt = 0; mt < 2; ++mt)
                #pragma unroll
                for (int nt = 0; nt < 4; ++nt) {
                    int ks2 = 4 * w + nt;
                    uint32_t* bp = hAU + (mt * 32 + ks2) * 128;
                    bp[i00]     = f2tf32(fmaxf(c1[mt][nt][0], 0.f));
                    bp[i01]     = f2tf32(fmaxf(c1[mt][nt][1], 0.f));
                    bp[i00 + 1] = f2tf32(fmaxf(c1[mt][nt][2], 0.f));  // row g+8
                    bp[i01 + 1] = f2tf32(fmaxf(c1[mt][nt][3], 0.f));
                }
        }
        __syncthreads();

        // ---- GEMM2: seg[32][64] = h @ W2T (+b2i), warp w -> s in [8w,8w+8) ----
        float c2[2][4];
        {
            float bb0 = b2s[8 * w + 2 * tg];
            float bb1 = b2s[8 * w + 2 * tg + 1];
            c2[0][0] = bb0; c2[0][1] = bb1; c2[0][2] = bb0; c2[0][3] = bb1;
            c2[1][0] = bb0; c2[1][1] = bb1; c2[1][2] = bb0; c2[1][3] = bb1;
        }
        // half currently resident
        #pragma unroll
        for (int ksl = 0; ksl < 16; ++ksl) {
            int ks2 = cur * 16 + ksl;
            uint4 A0 = ((const uint4*)hAU)[(0 * 32 + ks2) * 32 + l];
            uint4 A1 = ((const uint4*)hAU)[(1 * 32 + ks2) * 32 + l];
            uint2 Bv = ((const uint2*)W2c)[(w * 16 + ksl) * 32 + l];
            MMA_TF32(c2[0], (&A0.x), Bv.x, Bv.y);
            MMA_TF32(c2[1], (&A1.x), Bv.x, Bv.y);
        }
        __syncthreads();   // W2c consumed
        {
            const float4* src = (const float4*)(g_W2p + (cur ^ 1) * 8192);
            float4*       dst = (float4*)W2c;
            #pragma unroll
            for (int r = 0; r < 8; ++r) dst[tid + 256 * r] = src[tid + 256 * r];
        }
        __syncthreads();
        #pragma unroll
        for (int ksl = 0; ksl < 16; ++ksl) {
            int ks2 = (cur ^ 1) * 16 + ksl;
            uint4 A0 = ((const uint4*)hAU)[(0 * 32 + ks2) * 32 + l];
            uint4 A1 = ((const uint4*)hAU)[(1 * 32 + ks2) * 32 + l];
            uint2 Bv = ((const uint2*)W2c)[(w * 16 + ksl) * 32 + l];
            MMA_TF32(c2[0], (&A0.x), Bv.x, Bv.y);
            MMA_TF32(c2[1], (&A1.x), Bv.x, Bv.y);
        }
        cur ^= 1;

        // ---- overlap-add, two phases (race-free plain adds) ----
        {
            int s0 = 8 * w + 2 * tg, s1 = s0 + 1;
            if (w < 4) {
                #pragma unroll
                for (int mt = 0; mt < 2; ++mt) {
                    int t0 = mt * 16 + g, t1 = t0 + 8;
                    sig[1 + 32 * t0 + s0] += c2[mt][0];
                    sig[1 + 32 * t0 + s1] += c2[mt][1];
                    sig[1 + 32 * t1 + s0] += c2[mt][2];
                    sig[1 + 32 * t1 + s1] += c2[mt][3];
                }
            }
            __syncthreads();
            if (w >= 4) {
                #pragma unroll
                for (int mt = 0; mt < 2; ++mt) {
                    int t0 = mt * 16 + g, t1 = t0 + 8;
                    sig[1 + 32 * t0 + s0] += c2[mt][0];
                    sig[1 + 32 * t0 + s1] += c2[mt][1];
                    sig[1 + 32 * t1 + s0] += c2[mt][2];
                    sig[1 + 32 * t1 + s1] += c2[mt][3];
                }
            }
            __syncthreads();
        }

        // ---- normalize + conv tap for this channel -> oac ----
        {
            float w0c = wcv[c * 3 + 0];
            float w1c = wcv[c * 3 + 1];
            float w2c = wcv[c * 3 + 2];
            for (int p = tid; p < SIG; p += 256) {
                float vm = sig[p]     * cinvf(p - 1);
                float v0 = sig[p + 1] * cinvf(p);
                float vp = sig[p + 2] * cinvf(p + 1);
                oac[p] += w0c * vm + w1c * v0 + w2c * vp;
            }
        }
        __syncthreads();
    }

    float bc = bconv[0];
    for (int p = tid; p < SIG; p += 256)
        out[(size_t)b * SIG + p] = oac[p] + bc;
}

// ---------------- launch ----------------
extern "C" void kernel_launch(void* const* d_in, const int* in_sizes, int n_in,
                              void* d_out, int out_size) {
    (void)in_sizes; (void)n_in; (void)out_size;
    const float* enc   = (const float*)d_in[0];
    const float* W1    = (const float*)d_in[1];
    const float* b1    = (const float*)d_in[2];
    const float* W2    = (const float*)d_in[3];
    const float* b2    = (const float*)d_in[4];
    const float* Winv  = (const float*)d_in[5];
    const float* binv  = (const float*)d_in[6];
    const float* Wconv = (const float*)d_in[7];
    const float* bconv = (const float*)d_in[8];
    float* out = (float*)d_out;

    cudaFuncSetAttribute(decoder_main, cudaFuncAttributeMaxDynamicSharedMemorySize,
                         SMEM_BYTES);

    prep_w1p<<<128, 256>>>(W1);
    prep_w2<<<64, 256>>>(W2, Winv, b2, binv);
    prep_w2p<<<64, 256>>>();
    decoder_main<<<NB, 256, SMEM_BYTES>>>(enc, b1, Wconv, bconv, out);
}

// round 5
// speedup vs baseline: 3.3803x; 1.3675x over previous
#include <cuda_runtime.h>
#include <cstdint>
#include <cstddef>

#define NB   1024
#define NC   8
#define NT   32
#define NE   128
#define NH   256
#define SEG  64
#define SIG  1056

// ---------------- device scratch (static; no allocations) ----------------
__device__ __align__(16) float g_W1p[8 * 16 * 32 * 8];   // 32768 tf32, GEMM1-B frag-packed
__device__ __align__(16) float g_W2T[NH * SEG];          // [h][s] = (Winv@W2)^T
__device__ __align__(16) float g_W2p[2 * 16 * 4 * 32 * 4]; // 16384 tf32, GEMM2-B frag-packed
__device__ __align__(16) float g_b2i[SEG];               // binv + Winv@b2

// ---------------- helpers ----------------
__device__ __forceinline__ uint32_t f2tf32(float x) {
    uint32_t u;
    asm("cvt.rna.tf32.f32 %0, %1;" : "=r"(u) : "f"(x));
    return u;
}

#define MMA_TF32(C, A, b0v, b1v)                                               \
    asm volatile(                                                              \
        "mma.sync.aligned.m16n8k8.row.col.f32.tf32.tf32.f32 "                  \
        "{%0,%1,%2,%3},{%4,%5,%6,%7},{%8,%9},{%0,%1,%2,%3};"                   \
        : "+f"((C)[0]), "+f"((C)[1]), "+f"((C)[2]), "+f"((C)[3])               \
        : "r"((A)[0]), "r"((A)[1]), "r"((A)[2]), "r"((A)[3]),                  \
          "r"(b0v), "r"(b1v))

// ---------------- prep kernels ----------------
// W1 [j=256][k=128] -> GEMM1-B frag pack:
// g_W1p[((w*16+ks)*32+l)*8 + v]; v = nt*2+hh; value = W1[32w+8nt+g][8ks+tg+4hh]
__global__ void prep_w1p(const float* __restrict__ W1) {
    int id = blockIdx.x * 256 + threadIdx.x;     // 32768
    int v  = id & 7;
    int l  = (id >> 3) & 31;
    int ks = (id >> 8) & 15;
    int w  = id >> 12;
    int g = l >> 2, tg = l & 3, nt = v >> 1, hh = v & 1;
    int j = 32 * w + 8 * nt + g;
    int k = 8 * ks + tg + 4 * hh;
    ((uint32_t*)g_W1p)[id] = f2tf32(W1[j * NE + k]);
}

// W2T[h][s] = sum_e Winv[s][e]*W2[e][h];  b2i[s] = binv[s] + Winv[s]·b2
__global__ void prep_w2(const float* __restrict__ W2, const float* __restrict__ Winv,
                        const float* __restrict__ b2, const float* __restrict__ binv) {
    int s = blockIdx.x;        // 64
    int h = threadIdx.x;       // 256
    const float* wr = Winv + s * NE;
    float acc = 0.f;
    #pragma unroll 4
    for (int e = 0; e < NE; ++e) acc += wr[e] * W2[e * NH + h];
    g_W2T[h * SEG + s] = acc;
    if (h == 0) {
        float t = 0.f;
        for (int e = 0; e < NE; ++e) t += wr[e] * b2[e];
        g_b2i[s] = binv[s] + t;
    }
}

// W2T -> GEMM2-B frag pack (K-split, n16 warp tiles):
// g_W2p[(((kh*16+ksl)*4+sw)*32+l)*4 + comp]; comp = nt2*2+hh
// value = W2T[h=8*(kh*16+ksl)+tg+4hh][s=16sw+8nt2+g]
__global__ void prep_w2p() {
    int id   = blockIdx.x * 256 + threadIdx.x;   // 16384
    int comp = id & 3;
    int l    = (id >> 2) & 31;
    int sw   = (id >> 7) & 3;
    int ksl  = (id >> 9) & 15;
    int kh   = (id >> 13) & 1;
    int g = l >> 2, tg = l & 3;
    int nt2 = comp >> 1, hh = comp & 1;
    int h = 8 * (kh * 16 + ksl) + tg + 4 * hh;
    int s = 16 * sw + 8 * nt2 + g;
    ((uint32_t*)g_W2p)[id] = f2tf32(g_W2T[h * SEG + s]);
}

// ---------------- main kernel ----------------
// smem float offsets
#define OFF_W2   0        // 16384  full W2 frag pack (tf32 bits)
#define OFF_ENC  16384    // 8448   2 enc tiles [32][132] (tf32 bits)
#define OFF_HA   24832    // 16384  2 hA buffers (tf32 bits, frag order)
#define OFF_SEG  41216    // 4352   2 partial seg [32][68]
#define OFF_SIG  45568    // 1058
#define OFF_OAC  46626    // 1056
#define OFF_B1   47682    // 256
#define OFF_B2   47938    // 64
#define OFF_WCV  48002    // 24
#define SMEM_FLOATS 48032
#define SMEM_BYTES  (SMEM_FLOATS * 4)

__device__ __forceinline__ float cinvf(int p) {
    return (p < 32 || p >= 1024) ? 1.0f : 0.5f;   // 1/overlap-count
}

__global__ __launch_bounds__(256, 1)
void decoder_main(const float* __restrict__ enc, const float* __restrict__ b1,
                  const float* __restrict__ Wconv, const float* __restrict__ bconv,
                  float* __restrict__ out) {
    extern __shared__ float sm[];
    const uint4* W2u  = (const uint4*)(sm + OFF_W2);
    uint32_t*    encU = (uint32_t*)(sm + OFF_ENC);
    uint32_t*    hAU  = (uint32_t*)(sm + OFF_HA);
    float*       seg0 = sm + OFF_SEG;
    float*       seg1 = sm + OFF_SEG + 2176;
    float*       sig  = sm + OFF_SIG;
    float*       oac  = sm + OFF_OAC;
    float*       b1s  = sm + OFF_B1;
    float*       b2s  = sm + OFF_B2;
    float*       wcv  = sm + OFF_WCV;

    const int tid = threadIdx.x;
    const int l   = tid & 31;
    const int w   = tid >> 5;       // warp 0..7
    const int g   = l >> 2;
    const int tg  = l & 3;
    const int b   = blockIdx.x;
    const int kh  = w >> 2;         // GEMM2 K-half
    const int sw  = w & 3;          // GEMM2 s-tile

    // ---- one-time staging: full W2 pack (64 KB), constants ----
    {
        const float4* src = (const float4*)g_W2p;
        float4*       dst = (float4*)(sm + OFF_W2);
        #pragma unroll
        for (int r = 0; r < 16; ++r) dst[tid + 256 * r] = src[tid + 256 * r];
    }
    b1s[tid] = b1[tid];
    if (tid < SEG) b2s[tid] = g_b2i[tid];
    if (tid < 24)  wcv[tid] = Wconv[tid];
    if (tid == 0) { sig[0] = 0.f; sig[1057] = 0.f; }
    for (int p = tid; p < SIG; p += 256) oac[p] = 0.f;
    __syncthreads();

    for (int cp = 0; cp < 4; ++cp) {
        // ---- stage enc for both channels of the pair -> tf32, stride 132 ----
        #pragma unroll
        for (int ch = 0; ch < 2; ++ch) {
            const float4* src =
                (const float4*)(enc + (size_t)(b * NC + 2 * cp + ch) * (NT * NE));
            uint32_t* eU = encU + ch * 4224;
            #pragma unroll
            for (int r = 0; r < 4; ++r) {
                int fi = tid + 256 * r;            // 0..1023
                float4 v = src[fi];
                int m = fi >> 5, kq = fi & 31;
                uint4 u;
                u.x = f2tf32(v.x); u.y = f2tf32(v.y);
                u.z = f2tf32(v.z); u.w = f2tf32(v.w);
                *(uint4*)(eU + m * 132 + kq * 4) = u;
            }
        }
        __syncthreads();

        // ---- GEMM1 both channels, B from global (loaded once per pair) ----
        float c1[2][2][4][4];                       // [ch][mt][nt][4]
        #pragma unroll
        for (int nt = 0; nt < 4; ++nt) {
            float bb0 = b1s[32 * w + 8 * nt + 2 * tg];
            float bb1 = b1s[32 * w + 8 * nt + 2 * tg + 1];
            #pragma unroll
            for (int ch = 0; ch < 2; ++ch)
                #pragma unroll
                for (int mt = 0; mt < 2; ++mt) {
                    c1[ch][mt][nt][0] = bb0; c1[ch][mt][nt][1] = bb1;
                    c1[ch][mt][nt][2] = bb0; c1[ch][mt][nt][3] = bb1;
                }
        }
        {
            const uint4* W1g = (const uint4*)g_W1p;
            int bidx = w * 1024 + l * 2;            // ((w*16+ks)*32+l)*2, ks=0
            uint4 B0 = __ldg(&W1g[bidx]);
            uint4 B1 = __ldg(&W1g[bidx + 1]);
            #pragma unroll
            for (int ks = 0; ks < 16; ++ks) {
                uint4 nB0, nB1;
                if (ks < 15) {
                    nB0 = __ldg(&W1g[bidx + 64 * (ks + 1)]);
                    nB1 = __ldg(&W1g[bidx + 64 * (ks + 1) + 1]);
                }
                uint32_t a[2][2][4];
                #pragma unroll
                for (int ch = 0; ch < 2; ++ch) {
                    const uint32_t* eU = encU + ch * 4224;
                    #pragma unroll
                    for (int mt = 0; mt < 2; ++mt) {
                        int r0 = (mt * 16 + g) * 132;
                        int k0 = 8 * ks + tg;
                        a[ch][mt][0] = eU[r0 + k0];
                        a[ch][mt][1] = eU[r0 + 8 * 132 + k0];
                        a[ch][mt][2] = eU[r0 + k0 + 4];
                        a[ch][mt][3] = eU[r0 + 8 * 132 + k0 + 4];
                    }
                }
                #pragma unroll
                for (int ch = 0; ch < 2; ++ch)
                    #pragma unroll
                    for (int mt = 0; mt < 2; ++mt) {
                        MMA_TF32(c1[ch][mt][0], a[ch][mt], B0.x, B0.y);
                        MMA_TF32(c1[ch][mt][1], a[ch][mt], B0.z, B0.w);
                        MMA_TF32(c1[ch][mt][2], a[ch][mt], B1.x, B1.y);
                        MMA_TF32(c1[ch][mt][3], a[ch][mt], B1.z, B1.w);
                    }
                B0 = nB0; B1 = nB1;
            }
        }

        // ---- epilogue: ReLU + tf32 + scatter into GEMM2-A fragment order ----
        {
            int col0 = 2 * tg, col1 = 2 * tg + 1;
            int i00 = (4 * g + (col0 & 3)) * 4 + 2 * (col0 >= 4);
            int i01 = (4 * g + (col1 & 3)) * 4 + 2 * (col1 >= 4);
            #pragma unroll
            for (int ch = 0; ch < 2; ++ch)
                #pragma unroll
                for (int mt = 0; mt < 2; ++mt)
                    #pragma unroll
                    for (int nt = 0; nt < 4; ++nt) {
                        uint32_t* bp =
                            hAU + ch * 8192 + (mt * 32 + (4 * w + nt)) * 128;
                        uint2 u0, u1;
                        u0.x = f2tf32(fmaxf(c1[ch][mt][nt][0], 0.f));
                        u0.y = f2tf32(fmaxf(c1[ch][mt][nt][2], 0.f));
                        u1.x = f2tf32(fmaxf(c1[ch][mt][nt][1], 0.f));
                        u1.y = f2tf32(fmaxf(c1[ch][mt][nt][3], 0.f));
                        *(uint2*)(bp + i00) = u0;
                        *(uint2*)(bp + i01) = u1;
                    }
        }
        __syncthreads();

        for (int sub = 0; sub < 2; ++sub) {
            // ---- GEMM2 (K-split by warp half, n16 per warp) ----
            const uint4* hU4 = (const uint4*)(hAU + sub * 8192);
            float c2[2][2][4];                      // [mt][nt2][4]
            #pragma unroll
            for (int nt2 = 0; nt2 < 2; ++nt2) {
                float bb0 = (kh == 0) ? b2s[16 * sw + 8 * nt2 + 2 * tg] : 0.f;
                float bb1 = (kh == 0) ? b2s[16 * sw + 8 * nt2 + 2 * tg + 1] : 0.f;
                #pragma unroll
                for (int mt = 0; mt < 2; ++mt) {
                    c2[mt][nt2][0] = bb0; c2[mt][nt2][1] = bb1;
                    c2[mt][nt2][2] = bb0; c2[mt][nt2][3] = bb1;
                }
            }
            #pragma unroll
            for (int ksl = 0; ksl < 16; ++ksl) {
                int ks2 = kh * 16 + ksl;
                uint4 A0 = hU4[(0 * 32 + ks2) * 32 + l];
                uint4 A1 = hU4[(1 * 32 + ks2) * 32 + l];
                uint4 Bv = W2u[((kh * 16 + ksl) * 4 + sw) * 32 + l];
                MMA_TF32(c2[0][0], (&A0.x), Bv.x, Bv.y);
                MMA_TF32(c2[0][1], (&A0.x), Bv.z, Bv.w);
                MMA_TF32(c2[1][0], (&A1.x), Bv.x, Bv.y);
                MMA_TF32(c2[1][1], (&A1.x), Bv.z, Bv.w);
            }

            // ---- store partial seg (kh -> its own buffer, no RMW) ----
            {
                float* sp = (kh == 0) ? seg0 : seg1;
                #pragma unroll
                for (int mt = 0; mt < 2; ++mt)
                    #pragma unroll
                    for (int nt2 = 0; nt2 < 2; ++nt2) {
                        int s0 = 16 * sw + 8 * nt2 + 2 * tg;
                        float2 v0 = make_float2(c2[mt][nt2][0], c2[mt][nt2][1]);
                        float2 v1 = make_float2(c2[mt][nt2][2], c2[mt][nt2][3]);
                        *(float2*)&sp[(mt * 16 + g) * 68 + s0]     = v0;
                        *(float2*)&sp[(mt * 16 + g + 8) * 68 + s0] = v1;
                    }
            }
            __syncthreads();

            // ---- overlap-add + normalize -> sig (conflict-free linear) ----
            for (int p = tid; p < SIG; p += 256) {
                int t = p >> 5, s = p & 31;
                float v = 0.f;
                if (t < 32) v += seg0[t * 68 + s] + seg1[t * 68 + s];
                if (t > 0)  v += seg0[(t - 1) * 68 + s + 32] + seg1[(t - 1) * 68 + s + 32];
                sig[1 + p] = v * cinvf(p);
            }
            __syncthreads();

            // ---- conv tap for this channel -> oac ----
            {
                int c = 2 * cp + sub;
                float w0c = wcv[c * 3 + 0];
                float w1c = wcv[c * 3 + 1];
                float w2c = wcv[c * 3 + 2];
                for (int p = tid; p < SIG; p += 256)
                    oac[p] += w0c * sig[p] + w1c * sig[p + 1] + w2c * sig[p + 2];
            }
            __syncthreads();
        }
    }

    float bc = bconv[0];
    for (int p = tid; p < SIG; p += 256)
        out[(size_t)b * SIG + p] = oac[p] + bc;
}

// ---------------- launch ----------------
extern "C" void kernel_launch(void* const* d_in, const int* in_sizes, int n_in,
                              void* d_out, int out_size) {
    (void)in_sizes; (void)n_in; (void)out_size;
    const float* enc   = (const float*)d_in[0];
    const float* W1    = (const float*)d_in[1];
    const float* b1    = (const float*)d_in[2];
    const float* W2    = (const float*)d_in[3];
    const float* b2    = (const float*)d_in[4];
    const float* Winv  = (const float*)d_in[5];
    const float* binv  = (const float*)d_in[6];
    const float* Wconv = (const float*)d_in[7];
    const float* bconv = (const float*)d_in[8];
    float* out = (float*)d_out;

    cudaFuncSetAttribute(decoder_main, cudaFuncAttributeMaxDynamicSharedMemorySize,
                         SMEM_BYTES);

    prep_w1p<<<128, 256>>>(W1);
    prep_w2<<<64, 256>>>(W2, Winv, b2, binv);
    prep_w2p<<<64, 256>>>();
    decoder_main<<<NB, 256, SMEM_BYTES>>>(enc, b1, Wconv, bconv, out);
}

// round 6
// speedup vs baseline: 3.8127x; 1.1279x over previous
#include <cuda_runtime.h>
#include <cstdint>
#include <cstddef>

#define NB   1024
#define NC   8
#define NT   32
#define NE   128
#define NH   256
#define SEG  64
#define SIG  1056

// ---------------- device scratch (static; no allocations) ----------------
__device__ __align__(16) float g_W1p[8 * 16 * 32 * 8];     // 32768 tf32, GEMM1-B frag pack
__device__ __align__(16) float g_W2T[NH * SEG];            // [h][s] = (Winv@W2)^T
__device__ __align__(16) float g_W2p[2 * 16 * 4 * 32 * 4]; // 16384 tf32, GEMM2-B frag pack
__device__ __align__(16) float g_b2i[SEG];                 // binv + Winv@b2

// ---------------- helpers ----------------
__device__ __forceinline__ uint32_t f2tf32(float x) {
    uint32_t u;
    asm("cvt.rna.tf32.f32 %0, %1;" : "=r"(u) : "f"(x));
    return u;
}

#define MMA_TF32(C, A, b0v, b1v)                                               \
    asm volatile(                                                              \
        "mma.sync.aligned.m16n8k8.row.col.f32.tf32.tf32.f32 "                  \
        "{%0,%1,%2,%3},{%4,%5,%6,%7},{%8,%9},{%0,%1,%2,%3};"                   \
        : "+f"((C)[0]), "+f"((C)[1]), "+f"((C)[2]), "+f"((C)[3])               \
        : "r"((A)[0]), "r"((A)[1]), "r"((A)[2]), "r"((A)[3]),                  \
          "r"(b0v), "r"(b1v))

// ---------------- prep kernels ----------------
// W1 [j=256][k=128] -> GEMM1-B frag pack:
// g_W1p[((w*16+ks)*32+l)*8 + v]; v = nt*2+hh; value = W1[32w+8nt+g][8ks+tg+4hh]
__global__ void prep_w1p(const float* __restrict__ W1) {
    int id = blockIdx.x * 256 + threadIdx.x;     // 32768
    int v  = id & 7;
    int l  = (id >> 3) & 31;
    int ks = (id >> 8) & 15;
    int w  = id >> 12;
    int g = l >> 2, tg = l & 3, nt = v >> 1, hh = v & 1;
    int j = 32 * w + 8 * nt + g;
    int k = 8 * ks + tg + 4 * hh;
    ((uint32_t*)g_W1p)[id] = f2tf32(W1[j * NE + k]);
}

// W2T[h][s] = sum_e Winv[s][e]*W2[e][h];  b2i[s] = binv[s] + Winv[s]·b2
__global__ void prep_w2(const float* __restrict__ W2, const float* __restrict__ Winv,
                        const float* __restrict__ b2, const float* __restrict__ binv) {
    int s = blockIdx.x;        // 64
    int h = threadIdx.x;       // 256
    const float* wr = Winv + s * NE;
    float acc = 0.f;
    #pragma unroll 4
    for (int e = 0; e < NE; ++e) acc += wr[e] * W2[e * NH + h];
    g_W2T[h * SEG + s] = acc;
    if (h == 0) {
        float t = 0.f;
        for (int e = 0; e < NE; ++e) t += wr[e] * b2[e];
        g_b2i[s] = binv[s] + t;
    }
}

// W2T -> GEMM2-B frag pack (K-split 2, n16 warp tiles):
// g_W2p[(((kh*16+ksl)*4+sw)*32+l)*4 + comp]; comp = nt2*2+hh
// value = W2T[h=8*(kh*16+ksl)+tg+4hh][s=16sw+8nt2+g]
__global__ void prep_w2p() {
    int id   = blockIdx.x * 256 + threadIdx.x;   // 16384
    int comp = id & 3;
    int l    = (id >> 2) & 31;
    int sw   = (id >> 7) & 3;
    int ksl  = (id >> 9) & 15;
    int kh   = (id >> 13) & 1;
    int g = l >> 2, tg = l & 3;
    int nt2 = comp >> 1, hh = comp & 1;
    int h = 8 * (kh * 16 + ksl) + tg + 4 * hh;
    int s = 16 * sw + 8 * nt2 + g;
    ((uint32_t*)g_W2p)[id] = f2tf32(g_W2T[h * SEG + s]);
}

// ---------------- main kernel ----------------
// smem float offsets (77 KB -> 2 CTAs/SM)
#define OFF_ENC  0        // 4224   enc tile [32][132] (tf32 bits)
#define OFF_HA   4224     // 8192   hA (tf32 bits, GEMM2-A frag order)
#define OFF_SEG  12416    // 4352   2 partial seg [32][68]
#define OFF_SIG  16768    // 1058
#define OFF_OAC  17826    // 1056
#define OFF_B1   18882    // 256
#define OFF_B2   19138    // 64
#define OFF_WCV  19202    // 24
#define SMEM_FLOATS 19232
#define SMEM_BYTES  (SMEM_FLOATS * 4)

__device__ __forceinline__ float cinvf(int p) {
    return (p < 32 || p >= 1024) ? 1.0f : 0.5f;   // 1/overlap-count
}

__global__ __launch_bounds__(256, 2)
void decoder_main(const float* __restrict__ enc, const float* __restrict__ b1,
                  const float* __restrict__ Wconv, const float* __restrict__ bconv,
                  float* __restrict__ out) {
    extern __shared__ float sm[];
    uint32_t* encU = (uint32_t*)(sm + OFF_ENC);
    uint32_t* hAU  = (uint32_t*)(sm + OFF_HA);
    float*    seg0 = sm + OFF_SEG;
    float*    seg1 = sm + OFF_SEG + 2176;
    float*    sig  = sm + OFF_SIG;
    float*    oac  = sm + OFF_OAC;
    float*    b1s  = sm + OFF_B1;
    float*    b2s  = sm + OFF_B2;
    float*    wcv  = sm + OFF_WCV;

    const int tid = threadIdx.x;
    const int l   = tid & 31;
    const int w   = tid >> 5;       // warp 0..7
    const int g   = l >> 2;
    const int tg  = l & 3;
    const int b   = blockIdx.x;
    const int kh  = w >> 2;         // GEMM2 K-half
    const int sw  = w & 3;          // GEMM2 s-tile

    b1s[tid] = b1[tid];
    if (tid < SEG) b2s[tid] = g_b2i[tid];
    if (tid < 24)  wcv[tid] = Wconv[tid];
    if (tid == 0) { sig[0] = 0.f; sig[1057] = 0.f; }
    for (int p = tid; p < SIG; p += 256) oac[p] = 0.f;
    __syncthreads();

    for (int c = 0; c < NC; ++c) {
        // ---- stage enc tile -> tf32, padded stride 132 ----
        {
            const float4* src =
                (const float4*)(enc + (size_t)(b * NC + c) * (NT * NE));
            #pragma unroll
            for (int r = 0; r < 4; ++r) {
                int fi = tid + 256 * r;            // 0..1023
                float4 v = src[fi];
                int m = fi >> 5, kq = fi & 31;
                uint4 u;
                u.x = f2tf32(v.x); u.y = f2tf32(v.y);
                u.z = f2tf32(v.z); u.w = f2tf32(v.w);
                *(uint4*)(encU + m * 132 + kq * 4) = u;
            }
        }
        __syncthreads();

        // ---- GEMM1: h[32][256] = enc @ W1^T (+b1), warp w -> j in [32w,32w+32) ----
        float c1[2][4][4];
        #pragma unroll
        for (int nt = 0; nt < 4; ++nt) {
            float bb0 = b1s[32 * w + 8 * nt + 2 * tg];
            float bb1 = b1s[32 * w + 8 * nt + 2 * tg + 1];
            #pragma unroll
            for (int mt = 0; mt < 2; ++mt) {
                c1[mt][nt][0] = bb0; c1[mt][nt][1] = bb1;
                c1[mt][nt][2] = bb0; c1[mt][nt][3] = bb1;
            }
        }
        {
            const uint4* W1g = (const uint4*)g_W1p;
            int bidx = w * 1024 + l * 2;            // ((w*16+ks)*32+l)*2, ks=0
            uint4 B0 = __ldg(&W1g[bidx]);
            uint4 B1 = __ldg(&W1g[bidx + 1]);
            #pragma unroll
            for (int ks = 0; ks < 16; ++ks) {
                uint4 nB0, nB1;
                if (ks < 15) {
                    nB0 = __ldg(&W1g[bidx + 64 * (ks + 1)]);
                    nB1 = __ldg(&W1g[bidx + 64 * (ks + 1) + 1]);
                }
                uint32_t a[2][4];
                #pragma unroll
                for (int mt = 0; mt < 2; ++mt) {
                    int r0 = (mt * 16 + g) * 132;
                    int k0 = 8 * ks + tg;
                    a[mt][0] = encU[r0 + k0];
                    a[mt][1] = encU[r0 + 8 * 132 + k0];
                    a[mt][2] = encU[r0 + k0 + 4];
                    a[mt][3] = encU[r0 + 8 * 132 + k0 + 4];
                }
                #pragma unroll
                for (int mt = 0; mt < 2; ++mt) {
                    MMA_TF32(c1[mt][0], a[mt], B0.x, B0.y);
                    MMA_TF32(c1[mt][1], a[mt], B0.z, B0.w);
                    MMA_TF32(c1[mt][2], a[mt], B1.x, B1.y);
                    MMA_TF32(c1[mt][3], a[mt], B1.z, B1.w);
                }
                B0 = nB0; B1 = nB1;
            }
        }

        // ---- epilogue: ReLU + tf32 + scatter into GEMM2-A fragment order ----
        {
            int col0 = 2 * tg, col1 = 2 * tg + 1;
            int i00 = (4 * g + (col0 & 3)) * 4 + 2 * (col0 >= 4);
            int i01 = (4 * g + (col1 & 3)) * 4 + 2 * (col1 >= 4);
            #pragma unroll
            for (int mt = 0; mt < 2; ++mt)
                #pragma unroll
                for (int nt = 0; nt < 4; ++nt) {
                    uint32_t* bp = hAU + (mt * 32 + (4 * w + nt)) * 128;
                    uint2 u0, u1;
                    u0.x = f2tf32(fmaxf(c1[mt][nt][0], 0.f));
                    u0.y = f2tf32(fmaxf(c1[mt][nt][2], 0.f));
                    u1.x = f2tf32(fmaxf(c1[mt][nt][1], 0.f));
                    u1.y = f2tf32(fmaxf(c1[mt][nt][3], 0.f));
                    *(uint2*)(bp + i00) = u0;
                    *(uint2*)(bp + i01) = u1;
                }
        }
        __syncthreads();

        // ---- GEMM2: seg[32][64] = h @ W2T (+b2i), K-split by warp half ----
        {
            const uint4* hU4 = (const uint4*)hAU;
            const uint4* W2g = (const uint4*)g_W2p;
            float c2[2][2][4];                      // [mt][nt2][4]
            #pragma unroll
            for (int nt2 = 0; nt2 < 2; ++nt2) {
                float bb0 = (kh == 0) ? b2s[16 * sw + 8 * nt2 + 2 * tg] : 0.f;
                float bb1 = (kh == 0) ? b2s[16 * sw + 8 * nt2 + 2 * tg + 1] : 0.f;
                #pragma unroll
                for (int mt = 0; mt < 2; ++mt) {
                    c2[mt][nt2][0] = bb0; c2[mt][nt2][1] = bb1;
                    c2[mt][nt2][2] = bb0; c2[mt][nt2][3] = bb1;
                }
            }
            int b2idx = ((kh * 16) * 4 + sw) * 32 + l;
            uint4 Bv = __ldg(&W2g[b2idx]);
            #pragma unroll
            for (int ksl = 0; ksl < 16; ++ksl) {
                uint4 nBv;
                if (ksl < 15) nBv = __ldg(&W2g[b2idx + 128 * (ksl + 1)]);
                int ks2 = kh * 16 + ksl;
                uint4 A0 = hU4[(0 * 32 + ks2) * 32 + l];
                uint4 A1 = hU4[(1 * 32 + ks2) * 32 + l];
                MMA_TF32(c2[0][0], (&A0.x), Bv.x, Bv.y);
                MMA_TF32(c2[0][1], (&A0.x), Bv.z, Bv.w);
                MMA_TF32(c2[1][0], (&A1.x), Bv.x, Bv.y);
                MMA_TF32(c2[1][1], (&A1.x), Bv.z, Bv.w);
                Bv = nBv;
            }

            // ---- store partial seg (kh -> its own buffer, no RMW) ----
            float* sp = (kh == 0) ? seg0 : seg1;
            #pragma unroll
            for (int mt = 0; mt < 2; ++mt)
                #pragma unroll
                for (int nt2 = 0; nt2 < 2; ++nt2) {
                    int s0 = 16 * sw + 8 * nt2 + 2 * tg;
                    float2 v0 = make_float2(c2[mt][nt2][0], c2[mt][nt2][1]);
                    float2 v1 = make_float2(c2[mt][nt2][2], c2[mt][nt2][3]);
                    *(float2*)&sp[(mt * 16 + g) * 68 + s0]     = v0;
                    *(float2*)&sp[(mt * 16 + g + 8) * 68 + s0] = v1;
                }
        }
        __syncthreads();

        // ---- overlap-add + normalize -> sig (conflict-free linear) ----
        for (int p = tid; p < SIG; p += 256) {
            int t = p >> 5, s = p & 31;
            float v = 0.f;
            if (t < 32) v += seg0[t * 68 + s] + seg1[t * 68 + s];
            if (t > 0)  v += seg0[(t - 1) * 68 + s + 32] + seg1[(t - 1) * 68 + s + 32];
            sig[1 + p] = v * cinvf(p);
        }
        __syncthreads();

        // ---- conv tap for this channel -> oac ----
        {
            float w0c = wcv[c * 3 + 0];
            float w1c = wcv[c * 3 + 1];
            float w2c = wcv[c * 3 + 2];
            for (int p = tid; p < SIG; p += 256)
                oac[p] += w0c * sig[p] + w1c * sig[p + 1] + w2c * sig[p + 2];
        }
        __syncthreads();
    }

    float bc = bconv[0];
    for (int p = tid; p < SIG; p += 256)
        out[(size_t)b * SIG + p] = oac[p] + bc;
}

// ---------------- launch ----------------
extern "C" void kernel_launch(void* const* d_in, const int* in_sizes, int n_in,
                              void* d_out, int out_size) {
    (void)in_sizes; (void)n_in; (void)out_size;
    const float* enc   = (const float*)d_in[0];
    const float* W1    = (const float*)d_in[1];
    const float* b1    = (const float*)d_in[2];
    const float* W2    = (const float*)d_in[3];
    const float* b2    = (const float*)d_in[4];
    const float* Winv  = (const float*)d_in[5];
    const float* binv  = (const float*)d_in[6];
    const float* Wconv = (const float*)d_in[7];
    const float* bconv = (const float*)d_in[8];
    float* out = (float*)d_out;

    cudaFuncSetAttribute(decoder_main, cudaFuncAttributeMaxDynamicSharedMemorySize,
                         SMEM_BYTES);

    prep_w1p<<<128, 256>>>(W1);
    prep_w2<<<64, 256>>>(W2, Winv, b2, binv);
    prep_w2p<<<64, 256>>>();
    decoder_main<<<NB, 256, SMEM_BYTES>>>(enc, b1, Wconv, bconv, out);
}

// round 7
// speedup vs baseline: 3.9808x; 1.0441x over previous
#include <cuda_runtime.h>
#include <cstdint>
#include <cstddef>

#define NB   1024
#define NC   8
#define NT   32
#define NE   128
#define NH   256
#define SEG  64
#define SIG  1056

// ---------------- device scratch (static; no allocations) ----------------
__device__ __align__(16) float g_W1p[8 * 16 * 32 * 8];     // 32768 tf32, GEMM1-B frag pack
__device__ __align__(16) float g_W2T[NH * SEG];            // [h][s] = (Winv@W2)^T
__device__ __align__(16) float g_W2p[4 * 8 * 2 * 32 * 8];  // 16384 tf32, GEMM2-B frag pack (K4)
__device__ __align__(16) float g_b2i[SEG];                 // binv + Winv@b2

// ---------------- helpers ----------------
__device__ __forceinline__ uint32_t f2tf32(float x) {
    uint32_t u;
    asm("cvt.rna.tf32.f32 %0, %1;" : "=r"(u) : "f"(x));
    return u;
}

__device__ __forceinline__ void cpasync16(uint32_t saddr, const void* gaddr) {
    asm volatile("cp.async.cg.shared.global [%0], [%1], 16;" :: "r"(saddr), "l"(gaddr));
}
#define CPASYNC_COMMIT() asm volatile("cp.async.commit_group;")
#define CPASYNC_WAIT0()  asm volatile("cp.async.wait_group 0;")

#define MMA_TF32(C, A, b0v, b1v)                                               \
    asm volatile(                                                              \
        "mma.sync.aligned.m16n8k8.row.col.f32.tf32.tf32.f32 "                  \
        "{%0,%1,%2,%3},{%4,%5,%6,%7},{%8,%9},{%0,%1,%2,%3};"                   \
        : "+f"((C)[0]), "+f"((C)[1]), "+f"((C)[2]), "+f"((C)[3])               \
        : "r"((A)[0]), "r"((A)[1]), "r"((A)[2]), "r"((A)[3]),                  \
          "r"(b0v), "r"(b1v))

// ---------------- prep kernels ----------------
// W1 [j=256][k=128] -> GEMM1-B frag pack:
// g_W1p[((w*16+ks)*32+l)*8 + v]; v = nt*2+hh; value = W1[32w+8nt+g][8ks+tg+4hh]
__global__ void prep_w1p(const float* __restrict__ W1) {
    int id = blockIdx.x * 256 + threadIdx.x;     // 32768
    int v  = id & 7;
    int l  = (id >> 3) & 31;
    int ks = (id >> 8) & 15;
    int w  = id >> 12;
    int g = l >> 2, tg = l & 3, nt = v >> 1, hh = v & 1;
    int j = 32 * w + 8 * nt + g;
    int k = 8 * ks + tg + 4 * hh;
    ((uint32_t*)g_W1p)[id] = f2tf32(W1[j * NE + k]);
}

// W2T[h][s] = sum_e Winv[s][e]*W2[e][h];  b2i[s] = binv[s] + Winv[s]·b2
__global__ void prep_w2(const float* __restrict__ W2, const float* __restrict__ Winv,
                        const float* __restrict__ b2, const float* __restrict__ binv) {
    int s = blockIdx.x;        // 64
    int h = threadIdx.x;       // 256
    const float* wr = Winv + s * NE;
    float acc = 0.f;
    #pragma unroll 4
    for (int e = 0; e < NE; ++e) acc += wr[e] * W2[e * NH + h];
    g_W2T[h * SEG + s] = acc;
    if (h == 0) {
        float t = 0.f;
        for (int e = 0; e < NE; ++e) t += wr[e] * b2[e];
        g_b2i[s] = binv[s] + t;
    }
}

// W2T -> GEMM2-B frag pack (K-split 4, s-split 2, n32 warp tiles):
// g_W2p[(((kq*8+ksl)*2+sh)*32+l)*8 + comp]; comp = nt2*2+hh
// value = W2T[h=8*(kq*8+ksl)+tg+4hh][s=32sh+8nt2+g]
__global__ void prep_w2p() {
    int id   = blockIdx.x * 256 + threadIdx.x;   // 16384
    int comp = id & 7;
    int l    = (id >> 3) & 31;
    int sh   = (id >> 8) & 1;
    int ksl  = (id >> 9) & 7;
    int kq   = (id >> 12) & 3;
    int g = l >> 2, tg = l & 3;
    int nt2 = comp >> 1, hh = comp & 1;
    int h = 8 * (kq * 8 + ksl) + tg + 4 * hh;
    int s = 32 * sh + 8 * nt2 + g;
    ((uint32_t*)g_W2p)[id] = f2tf32(g_W2T[h * SEG + s]);
}

// ---------------- main kernel ----------------
// smem float offsets (~104.5 KB -> 2 CTAs/SM)
#define OFF_ENC  0        // 8448   2 enc tiles [32][132] (raw fp32)
#define OFF_HA   8448     // 8192   hA (tf32 bits, GEMM2-A frag order)
#define OFF_SEG  16640    // 8704   4 partial seg [32][68]
#define OFF_SIG  25344    // 1058
#define OFF_B1   26402    // 256
#define OFF_B2   26658    // 64
#define OFF_WCV  26722    // 24
#define SMEM_FLOATS 26752
#define SMEM_BYTES  (SMEM_FLOATS * 4)

__device__ __forceinline__ float cinvf(int p) {
    return (p < 32 || p >= 1024) ? 1.0f : 0.5f;   // 1/overlap-count
}

__global__ __launch_bounds__(256, 2)
void decoder_main(const float* __restrict__ enc, const float* __restrict__ b1,
                  const float* __restrict__ Wconv, const float* __restrict__ bconv,
                  float* __restrict__ out) {
    extern __shared__ float sm[];
    uint32_t* encU = (uint32_t*)(sm + OFF_ENC);
    uint32_t* hAU  = (uint32_t*)(sm + OFF_HA);
    float*    segB = sm + OFF_SEG;
    float*    sig  = sm + OFF_SIG;
    float*    b1s  = sm + OFF_B1;
    float*    b2s  = sm + OFF_B2;
    float*    wcv  = sm + OFF_WCV;
    const uint32_t smemBase = (uint32_t)__cvta_generic_to_shared(sm);

    const int tid = threadIdx.x;
    const int l   = tid & 31;
    const int w   = tid >> 5;       // warp 0..7
    const int g   = l >> 2;
    const int tg  = l & 3;
    const int b   = blockIdx.x;
    const int kq  = w >> 1;         // GEMM2 K-quarter
    const int sh  = w & 1;          // GEMM2 s-half

    b1s[tid] = b1[tid];
    if (tid < SEG) b2s[tid] = g_b2i[tid];
    if (tid < 24)  wcv[tid] = Wconv[tid];
    if (tid == 0) { sig[0] = 0.f; sig[1057] = 0.f; }

    float oa[5];                    // out accumulator: p = tid + 256*i
    #pragma unroll
    for (int i = 0; i < 5; ++i) oa[i] = 0.f;

    for (int cp = 0; cp < 4; ++cp) {
        // ---- stage enc pair via cp.async (raw fp32, stride 132) ----
        #pragma unroll
        for (int ch = 0; ch < 2; ++ch) {
            const float* src = enc + (size_t)(b * NC + 2 * cp + ch) * (NT * NE);
            #pragma unroll
            for (int r = 0; r < 4; ++r) {
                int fi = tid + 256 * r;            // float4 index 0..1023
                int m = fi >> 5, kk = fi & 31;
                cpasync16(smemBase + (uint32_t)(OFF_ENC + ch * 4224 + m * 132 + kk * 4) * 4,
                          src + fi * 4);
            }
        }
        CPASYNC_COMMIT();
        CPASYNC_WAIT0();
        __syncthreads();

        // ---- GEMM1 both channels, B loaded once per pair ----
        float c1[2][2][4][4];                       // [ch][mt][nt][4]
        #pragma unroll
        for (int nt = 0; nt < 4; ++nt) {
            float bb0 = b1s[32 * w + 8 * nt + 2 * tg];
            float bb1 = b1s[32 * w + 8 * nt + 2 * tg + 1];
            #pragma unroll
            for (int ch = 0; ch < 2; ++ch)
                #pragma unroll
                for (int mt = 0; mt < 2; ++mt) {
                    c1[ch][mt][nt][0] = bb0; c1[ch][mt][nt][1] = bb1;
                    c1[ch][mt][nt][2] = bb0; c1[ch][mt][nt][3] = bb1;
                }
        }
        {
            const uint4* W1g = (const uint4*)g_W1p;
            int bidx = w * 1024 + l * 2;
            uint4 B0 = __ldg(&W1g[bidx]);
            uint4 B1 = __ldg(&W1g[bidx + 1]);
            #pragma unroll
            for (int ks = 0; ks < 16; ++ks) {
                uint4 nB0, nB1;
                if (ks < 15) {
                    nB0 = __ldg(&W1g[bidx + 64 * (ks + 1)]);
                    nB1 = __ldg(&W1g[bidx + 64 * (ks + 1) + 1]);
                }
                #pragma unroll
                for (int ch = 0; ch < 2; ++ch) {
                    const uint32_t* eU = encU + ch * 4224;
                    #pragma unroll
                    for (int mt = 0; mt < 2; ++mt) {
                        uint32_t a[4];
                        int r0 = (mt * 16 + g) * 132;
                        int k0 = 8 * ks + tg;
                        a[0] = eU[r0 + k0];
                        a[1] = eU[r0 + 8 * 132 + k0];
                        a[2] = eU[r0 + k0 + 4];
                        a[3] = eU[r0 + 8 * 132 + k0 + 4];
                        MMA_TF32(c1[ch][mt][0], a, B0.x, B0.y);
                        MMA_TF32(c1[ch][mt][1], a, B0.z, B0.w);
                        MMA_TF32(c1[ch][mt][2], a, B1.x, B1.y);
                        MMA_TF32(c1[ch][mt][3], a, B1.z, B1.w);
                    }
                }
                B0 = nB0; B1 = nB1;
            }
        }

        for (int sub = 0; sub < 2; ++sub) {
            // ---- epilogue: ReLU + tf32 + scatter into GEMM2-A frag order ----
            {
                int col0 = 2 * tg, col1 = 2 * tg + 1;
                int i00 = (4 * g + (col0 & 3)) * 4 + 2 * (col0 >= 4);
                int i01 = (4 * g + (col1 & 3)) * 4 + 2 * (col1 >= 4);
                #pragma unroll
                for (int mt = 0; mt < 2; ++mt)
                    #pragma unroll
                    for (int nt = 0; nt < 4; ++nt) {
                        uint32_t* bp = hAU + (mt * 32 + (4 * w + nt)) * 128;
                        uint2 u0, u1;
                        u0.x = f2tf32(fmaxf(c1[sub][mt][nt][0], 0.f));
                        u0.y = f2tf32(fmaxf(c1[sub][mt][nt][2], 0.f));
                        u1.x = f2tf32(fmaxf(c1[sub][mt][nt][1], 0.f));
                        u1.y = f2tf32(fmaxf(c1[sub][mt][nt][3], 0.f));
                        *(uint2*)(bp + i00) = u0;
                        *(uint2*)(bp + i01) = u1;
                    }
            }
            __syncthreads();

            // ---- GEMM2: K-split 4, s-split 2, n32 per warp ----
            {
                const uint4* hU4 = (const uint4*)hAU;
                const uint4* W2g = (const uint4*)g_W2p;
                float c2[2][4][4];                  // [mt][nt2][4]
                #pragma unroll
                for (int nt2 = 0; nt2 < 4; ++nt2) {
                    float bb0 = (kq == 0) ? b2s[32 * sh + 8 * nt2 + 2 * tg] : 0.f;
                    float bb1 = (kq == 0) ? b2s[32 * sh + 8 * nt2 + 2 * tg + 1] : 0.f;
                    #pragma unroll
                    for (int mt = 0; mt < 2; ++mt) {
                        c2[mt][nt2][0] = bb0; c2[mt][nt2][1] = bb1;
                        c2[mt][nt2][2] = bb0; c2[mt][nt2][3] = bb1;
                    }
                }
                int b2idx = (((kq * 8) * 2 + sh) * 32 + l) * 2;
                uint4 Bv0 = __ldg(&W2g[b2idx]);
                uint4 Bv1 = __ldg(&W2g[b2idx + 1]);
                #pragma unroll
                for (int ksl = 0; ksl < 8; ++ksl) {
                    uint4 nBv0, nBv1;
                    if (ksl < 7) {
                        nBv0 = __ldg(&W2g[b2idx + 128 * (ksl + 1)]);
                        nBv1 = __ldg(&W2g[b2idx + 128 * (ksl + 1) + 1]);
                    }
                    int ks2 = kq * 8 + ksl;
                    uint4 A0 = hU4[(0 * 32 + ks2) * 32 + l];
                    uint4 A1 = hU4[(1 * 32 + ks2) * 32 + l];
                    MMA_TF32(c2[0][0], (&A0.x), Bv0.x, Bv0.y);
                    MMA_TF32(c2[0][1], (&A0.x), Bv0.z, Bv0.w);
                    MMA_TF32(c2[0][2], (&A0.x), Bv1.x, Bv1.y);
                    MMA_TF32(c2[0][3], (&A0.x), Bv1.z, Bv1.w);
                    MMA_TF32(c2[1][0], (&A1.x), Bv0.x, Bv0.y);
                    MMA_TF32(c2[1][1], (&A1.x), Bv0.z, Bv0.w);
                    MMA_TF32(c2[1][2], (&A1.x), Bv1.x, Bv1.y);
                    MMA_TF32(c2[1][3], (&A1.x), Bv1.z, Bv1.w);
                    Bv0 = nBv0; Bv1 = nBv1;
                }

                // ---- store partial seg (kq -> its own buffer, no RMW) ----
                float* sp = segB + kq * 2176;
                #pragma unroll
                for (int mt = 0; mt < 2; ++mt)
                    #pragma unroll
                    for (int nt2 = 0; nt2 < 4; ++nt2) {
                        int s0 = 32 * sh + 8 * nt2 + 2 * tg;
                        float2 v0 = make_float2(c2[mt][nt2][0], c2[mt][nt2][1]);
                        float2 v1 = make_float2(c2[mt][nt2][2], c2[mt][nt2][3]);
                        *(float2*)&sp[(mt * 16 + g) * 68 + s0]     = v0;
                        *(float2*)&sp[(mt * 16 + g + 8) * 68 + s0] = v1;
                    }
            }
            __syncthreads();

            // ---- overlap-add + normalize -> sig (conflict-free linear) ----
            for (int p = tid; p < SIG; p += 256) {
                int t = p >> 5, s = p & 31;
                float v = 0.f;
                #pragma unroll
                for (int q = 0; q < 4; ++q) {
                    const float* sp = segB + q * 2176;
                    if (t < 32) v += sp[t * 68 + s];
                    if (t > 0)  v += sp[(t - 1) * 68 + s + 32];
                }
                sig[1 + p] = v * cinvf(p);
            }
            __syncthreads();

            // ---- conv tap for this channel -> oa regs ----
            {
                int c = 2 * cp + sub;
                float w0c = wcv[c * 3 + 0];
                float w1c = wcv[c * 3 + 1];
                float w2c = wcv[c * 3 + 2];
                #pragma unroll
                for (int i = 0; i < 5; ++i) {
                    int p = tid + 256 * i;
                    if (p < SIG)
                        oa[i] += w0c * sig[p] + w1c * sig[p + 1] + w2c * sig[p + 2];
                }
            }
            __syncthreads();   // sig consumed; seg/hA reusable next sub/pair
        }
    }

    float bc = bconv[0];
    #pragma unroll
    for (int i = 0; i < 5; ++i) {
        int p = tid + 256 * i;
        if (p < SIG) out[(size_t)b * SIG + p] = oa[i] + bc;
    }
}

// ---------------- launch ----------------
extern "C" void kernel_launch(void* const* d_in, const int* in_sizes, int n_in,
                              void* d_out, int out_size) {
    (void)in_sizes; (void)n_in; (void)out_size;
    const float* enc   = (const float*)d_in[0];
    const float* W1    = (const float*)d_in[1];
    const float* b1    = (const float*)d_in[2];
    const float* W2    = (const float*)d_in[3];
    const float* b2    = (const float*)d_in[4];
    const float* Winv  = (const float*)d_in[5];
    const float* binv  = (const float*)d_in[6];
    const float* Wconv = (const float*)d_in[7];
    const float* bconv = (const float*)d_in[8];
    float* out = (float*)d_out;

    cudaFuncSetAttribute(decoder_main, cudaFuncAttributeMaxDynamicSharedMemorySize,
                         SMEM_BYTES);

    prep_w1p<<<128, 256>>>(W1);
    prep_w2<<<64, 256>>>(W2, Winv, b2, binv);
    prep_w2p<<<64, 256>>>();
    decoder_main<<<NB, 256, SMEM_BYTES>>>(enc, b1, Wconv, bconv, out);
}

// round 8
// speedup vs baseline: 4.0536x; 1.0183x over previous
#include <cuda_runtime.h>
#include <cstdint>
#include <cstddef>

#define NB   1024
#define NC   8
#define NT   32
#define NE   128
#define NH   256
#define SEG  64
#define SIG  1056

// ---------------- device scratch (static; no allocations) ----------------
__device__ __align__(16) float g_W1p[8 * 16 * 32 * 8];     // 32768 tf32, GEMM1-B frag pack
__device__ __align__(16) float g_W2T[NH * SEG];            // [h][s] = (Winv@W2)^T
__device__ __align__(16) float g_W2p[4 * 8 * 2 * 32 * 8];  // 16384 tf32, GEMM2-B frag pack (K4)
__device__ __align__(16) float g_b2i[SEG];                 // binv + Winv@b2

// ---------------- helpers ----------------
__device__ __forceinline__ uint32_t f2tf32(float x) {
    uint32_t u;
    asm("cvt.rna.tf32.f32 %0, %1;" : "=r"(u) : "f"(x));
    return u;
}

__device__ __forceinline__ void cpasync16(uint32_t saddr, const void* gaddr) {
    asm volatile("cp.async.cg.shared.global [%0], [%1], 16;" :: "r"(saddr), "l"(gaddr));
}
#define CPASYNC_COMMIT() asm volatile("cp.async.commit_group;")
#define CPASYNC_WAIT0()  asm volatile("cp.async.wait_group 0;")

#define MMA_TF32(C, A, b0v, b1v)                                               \
    asm volatile(                                                              \
        "mma.sync.aligned.m16n8k8.row.col.f32.tf32.tf32.f32 "                  \
        "{%0,%1,%2,%3},{%4,%5,%6,%7},{%8,%9},{%0,%1,%2,%3};"                   \
        : "+f"((C)[0]), "+f"((C)[1]), "+f"((C)[2]), "+f"((C)[3])               \
        : "r"((A)[0]), "r"((A)[1]), "r"((A)[2]), "r"((A)[3]),                  \
          "r"(b0v), "r"(b1v))

// ---------------- prep kernels ----------------
// W1 [j=256][k=128] -> GEMM1-B frag pack:
// g_W1p[((w*16+ks)*32+l)*8 + v]; v = nt*2+hh; value = W1[32w+8nt+g][8ks+tg+4hh]
__global__ void prep_w1p(const float* __restrict__ W1) {
    int id = blockIdx.x * 256 + threadIdx.x;     // 32768
    int v  = id & 7;
    int l  = (id >> 3) & 31;
    int ks = (id >> 8) & 15;
    int w  = id >> 12;
    int g = l >> 2, tg = l & 3, nt = v >> 1, hh = v & 1;
    int j = 32 * w + 8 * nt + g;
    int k = 8 * ks + tg + 4 * hh;
    ((uint32_t*)g_W1p)[id] = f2tf32(W1[j * NE + k]);
}

// W2T[h][s] = sum_e Winv[s][e]*W2[e][h];  b2i[s] = binv[s] + Winv[s]·b2
__global__ void prep_w2(const float* __restrict__ W2, const float* __restrict__ Winv,
                        const float* __restrict__ b2, const float* __restrict__ binv) {
    int s = blockIdx.x;        // 64
    int h = threadIdx.x;       // 256
    const float* wr = Winv + s * NE;
    float acc = 0.f;
    #pragma unroll 4
    for (int e = 0; e < NE; ++e) acc += wr[e] * W2[e * NH + h];
    g_W2T[h * SEG + s] = acc;
    if (h == 0) {
        float t = 0.f;
        for (int e = 0; e < NE; ++e) t += wr[e] * b2[e];
        g_b2i[s] = binv[s] + t;
    }
}

// W2T -> GEMM2-B frag pack (K-split 4, s-split 2, n32 warp tiles):
// g_W2p[(((kq*8+ksl)*2+sh)*32+l)*8 + comp]; comp = nt2*2+hh
// value = W2T[h=8*(kq*8+ksl)+tg+4hh][s=32sh+8nt2+g]
__global__ void prep_w2p() {
    int id   = blockIdx.x * 256 + threadIdx.x;   // 16384
    int comp = id & 7;
    int l    = (id >> 3) & 31;
    int sh   = (id >> 8) & 1;
    int ksl  = (id >> 9) & 7;
    int kq   = (id >> 12) & 3;
    int g = l >> 2, tg = l & 3;
    int nt2 = comp >> 1, hh = comp & 1;
    int h = 8 * (kq * 8 + ksl) + tg + 4 * hh;
    int s = 32 * sh + 8 * nt2 + g;
    ((uint32_t*)g_W2p)[id] = f2tf32(g_W2T[h * SEG + s]);
}

// ---------------- main kernel ----------------
// smem float offsets (~104.5 KB -> 2 CTAs/SM)
#define OFF_ENC  0        // 8448   2 enc tiles [32][132] (raw fp32)
#define OFF_HA   8448     // 8192   hA (tf32 bits, frag order, XOR-swizzled rows)
#define OFF_SEG  16640    // 8704   4 partial seg [32][68]
#define OFF_SIG  25344    // 1058
#define OFF_B1   26402    // 256
#define OFF_B2   26658    // 64
#define OFF_WCV  26722    // 24
#define SMEM_FLOATS 26752
#define SMEM_BYTES  (SMEM_FLOATS * 4)

__device__ __forceinline__ float cinvf(int p) {
    return (p < 32 || p >= 1024) ? 1.0f : 0.5f;   // 1/overlap-count
}

__global__ __launch_bounds__(256, 2)
void decoder_main(const float* __restrict__ enc, const float* __restrict__ b1,
                  const float* __restrict__ Wconv, const float* __restrict__ bconv,
                  float* __restrict__ out) {
    extern __shared__ float sm[];
    uint32_t* encU = (uint32_t*)(sm + OFF_ENC);
    uint32_t* hAU  = (uint32_t*)(sm + OFF_HA);
    float*    segB = sm + OFF_SEG;
    float*    sig  = sm + OFF_SIG;
    float*    b1s  = sm + OFF_B1;
    float*    b2s  = sm + OFF_B2;
    float*    wcv  = sm + OFF_WCV;
    const uint32_t smemBase = (uint32_t)__cvta_generic_to_shared(sm);

    const int tid = threadIdx.x;
    const int l   = tid & 31;
    const int w   = tid >> 5;       // warp 0..7
    const int g   = l >> 2;
    const int tg  = l & 3;
    const int b   = blockIdx.x;
    const int kq  = w >> 1;         // GEMM2 K-quarter
    const int sh  = w & 1;          // GEMM2 s-half
    const int lsw = l ^ ((l >> 3) & 7);   // swizzled chunk index for GEMM2 A reads

    b1s[tid] = b1[tid];
    if (tid < SEG) b2s[tid] = g_b2i[tid];
    if (tid < 24)  wcv[tid] = Wconv[tid];
    if (tid == 0) { sig[0] = 0.f; sig[1057] = 0.f; }

    float oa[5];                    // out accumulator: p = tid + 256*i
    #pragma unroll
    for (int i = 0; i < 5; ++i) oa[i] = 0.f;

    // ---- prologue: stage enc pair 0 via cp.async (raw fp32, stride 132) ----
    #pragma unroll
    for (int ch = 0; ch < 2; ++ch) {
        const float* src = enc + (size_t)(b * NC + ch) * (NT * NE);
        #pragma unroll
        for (int r = 0; r < 4; ++r) {
            int fi = tid + 256 * r;
            int m = fi >> 5, kk = fi & 31;
            cpasync16(smemBase + (uint32_t)(OFF_ENC + ch * 4224 + m * 132 + kk * 4) * 4,
                      src + fi * 4);
        }
    }
    CPASYNC_COMMIT();

    for (int cp = 0; cp < 4; ++cp) {
        CPASYNC_WAIT0();
        __syncthreads();

        // ---- GEMM1 both channels, B loaded once per pair ----
        float c1[2][2][4][4];                       // [ch][mt][nt][4]
        #pragma unroll
        for (int nt = 0; nt < 4; ++nt) {
            float bb0 = b1s[32 * w + 8 * nt + 2 * tg];
            float bb1 = b1s[32 * w + 8 * nt + 2 * tg + 1];
            #pragma unroll
            for (int ch = 0; ch < 2; ++ch)
                #pragma unroll
                for (int mt = 0; mt < 2; ++mt) {
                    c1[ch][mt][nt][0] = bb0; c1[ch][mt][nt][1] = bb1;
                    c1[ch][mt][nt][2] = bb0; c1[ch][mt][nt][3] = bb1;
                }
        }
        {
            const uint4* W1g = (const uint4*)g_W1p;
            int bidx = w * 1024 + l * 2;
            uint4 B0 = __ldg(&W1g[bidx]);
            uint4 B1 = __ldg(&W1g[bidx + 1]);
            #pragma unroll
            for (int ks = 0; ks < 16; ++ks) {
                uint4 nB0, nB1;
                if (ks < 15) {
                    nB0 = __ldg(&W1g[bidx + 64 * (ks + 1)]);
                    nB1 = __ldg(&W1g[bidx + 64 * (ks + 1) + 1]);
                }
                #pragma unroll
                for (int ch = 0; ch < 2; ++ch) {
                    const uint32_t* eU = encU + ch * 4224;
                    #pragma unroll
                    for (int mt = 0; mt < 2; ++mt) {
                        uint32_t a[4];
                        int r0 = (mt * 16 + g) * 132;
                        int k0 = 8 * ks + tg;
                        a[0] = eU[r0 + k0];
                        a[1] = eU[r0 + 8 * 132 + k0];
                        a[2] = eU[r0 + k0 + 4];
                        a[3] = eU[r0 + 8 * 132 + k0 + 4];
                        MMA_TF32(c1[ch][mt][0], a, B0.x, B0.y);
                        MMA_TF32(c1[ch][mt][1], a, B0.z, B0.w);
                        MMA_TF32(c1[ch][mt][2], a, B1.x, B1.y);
                        MMA_TF32(c1[ch][mt][3], a, B1.z, B1.w);
                    }
                }
                B0 = nB0; B1 = nB1;
            }
        }
        __syncthreads();   // all warps done reading enc

        // ---- prefetch next enc pair (overlaps epilogue/GEMM2/conv below) ----
        if (cp < 3) {
            #pragma unroll
            for (int ch = 0; ch < 2; ++ch) {
                const float* src =
                    enc + (size_t)(b * NC + 2 * (cp + 1) + ch) * (NT * NE);
                #pragma unroll
                for (int r = 0; r < 4; ++r) {
                    int fi = tid + 256 * r;
                    int m = fi >> 5, kk = fi & 31;
                    cpasync16(smemBase +
                              (uint32_t)(OFF_ENC + ch * 4224 + m * 132 + kk * 4) * 4,
                              src + fi * 4);
                }
            }
            CPASYNC_COMMIT();
        }

        for (int sub = 0; sub < 2; ++sub) {
            // ---- epilogue: ReLU + tf32 + swizzled scatter (2-wavefront floor) ----
            {
                int col0 = 2 * tg, col1 = 2 * tg + 1;
                int i00 = (4 * g + (col0 & 3)) * 4 + 2 * (col0 >= 4);
                int i01 = (4 * g + (col1 & 3)) * 4 + 2 * (col1 >= 4);
                int c00 = i00 >> 2, c01 = i01 >> 2;
                int j00 = ((c00 ^ ((c00 >> 3) & 7)) << 2) + (i00 & 3);
                int j01 = ((c01 ^ ((c01 >> 3) & 7)) << 2) + (i01 & 3);
                #pragma unroll
                for (int mt = 0; mt < 2; ++mt)
                    #pragma unroll
                    for (int nt = 0; nt < 4; ++nt) {
                        uint32_t* bp = hAU + (mt * 32 + (4 * w + nt)) * 128;
                        uint2 u0, u1;
                        u0.x = f2tf32(fmaxf(c1[sub][mt][nt][0], 0.f));
                        u0.y = f2tf32(fmaxf(c1[sub][mt][nt][2], 0.f));
                        u1.x = f2tf32(fmaxf(c1[sub][mt][nt][1], 0.f));
                        u1.y = f2tf32(fmaxf(c1[sub][mt][nt][3], 0.f));
                        *(uint2*)(bp + j00) = u0;
                        *(uint2*)(bp + j01) = u1;
                    }
            }
            __syncthreads();

            // ---- GEMM2: K-split 4, s-split 2, n32 per warp (swizzled A reads) ----
            {
                const uint4* hU4 = (const uint4*)hAU;
                const uint4* W2g = (const uint4*)g_W2p;
                float c2[2][4][4];                  // [mt][nt2][4]
                #pragma unroll
                for (int nt2 = 0; nt2 < 4; ++nt2) {
                    float bb0 = (kq == 0) ? b2s[32 * sh + 8 * nt2 + 2 * tg] : 0.f;
                    float bb1 = (kq == 0) ? b2s[32 * sh + 8 * nt2 + 2 * tg + 1] : 0.f;
                    #pragma unroll
                    for (int mt = 0; mt < 2; ++mt) {
                        c2[mt][nt2][0] = bb0; c2[mt][nt2][1] = bb1;
                        c2[mt][nt2][2] = bb0; c2[mt][nt2][3] = bb1;
                    }
                }
                int b2idx = (((kq * 8) * 2 + sh) * 32 + l) * 2;
                uint4 Bv0 = __ldg(&W2g[b2idx]);
                uint4 Bv1 = __ldg(&W2g[b2idx + 1]);
                #pragma unroll
                for (int ksl = 0; ksl < 8; ++ksl) {
                    uint4 nBv0, nBv1;
                    if (ksl < 7) {
                        nBv0 = __ldg(&W2g[b2idx + 128 * (ksl + 1)]);
                        nBv1 = __ldg(&W2g[b2idx + 128 * (ksl + 1) + 1]);
                    }
                    int ks2 = kq * 8 + ksl;
                    uint4 A0 = hU4[(0 * 32 + ks2) * 32 + lsw];
                    uint4 A1 = hU4[(1 * 32 + ks2) * 32 + lsw];
                    MMA_TF32(c2[0][0], (&A0.x), Bv0.x, Bv0.y);
                    MMA_TF32(c2[0][1], (&A0.x), Bv0.z, Bv0.w);
                    MMA_TF32(c2[0][2], (&A0.x), Bv1.x, Bv1.y);
                    MMA_TF32(c2[0][3], (&A0.x), Bv1.z, Bv1.w);
                    MMA_TF32(c2[1][0], (&A1.x), Bv0.x, Bv0.y);
                    MMA_TF32(c2[1][1], (&A1.x), Bv0.z, Bv0.w);
                    MMA_TF32(c2[1][2], (&A1.x), Bv1.x, Bv1.y);
                    MMA_TF32(c2[1][3], (&A1.x), Bv1.z, Bv1.w);
                    Bv0 = nBv0; Bv1 = nBv1;
                }

                // ---- store partial seg (kq -> its own buffer, no RMW) ----
                float* sp = segB + kq * 2176;
                #pragma unroll
                for (int mt = 0; mt < 2; ++mt)
                    #pragma unroll
                    for (int nt2 = 0; nt2 < 4; ++nt2) {
                        int s0 = 32 * sh + 8 * nt2 + 2 * tg;
                        float2 v0 = make_float2(c2[mt][nt2][0], c2[mt][nt2][1]);
                        float2 v1 = make_float2(c2[mt][nt2][2], c2[mt][nt2][3]);
                        *(float2*)&sp[(mt * 16 + g) * 68 + s0]     = v0;
                        *(float2*)&sp[(mt * 16 + g + 8) * 68 + s0] = v1;
                    }
            }
            __syncthreads();

            // ---- overlap-add + normalize -> sig (conflict-free linear) ----
            for (int p = tid; p < SIG; p += 256) {
                int t = p >> 5, s = p & 31;
                float v = 0.f;
                #pragma unroll
                for (int q = 0; q < 4; ++q) {
                    const float* sp = segB + q * 2176;
                    if (t < 32) v += sp[t * 68 + s];
                    if (t > 0)  v += sp[(t - 1) * 68 + s + 32];
                }
                sig[1 + p] = v * cinvf(p);
            }
            __syncthreads();

            // ---- conv tap for this channel -> oa regs ----
            {
                int c = 2 * cp + sub;
                float w0c = wcv[c * 3 + 0];
                float w1c = wcv[c * 3 + 1];
                float w2c = wcv[c * 3 + 2];
                #pragma unroll
                for (int i = 0; i < 5; ++i) {
                    int p = tid + 256 * i;
                    if (p < SIG)
                        oa[i] += w0c * sig[p] + w1c * sig[p + 1] + w2c * sig[p + 2];
                }
            }
            __syncthreads();   // sig consumed; hA/seg reusable next sub
        }
    }

    float bc = bconv[0];
    #pragma unroll
    for (int i = 0; i < 5; ++i) {
        int p = tid + 256 * i;
        if (p < SIG) out[(size_t)b * SIG + p] = oa[i] + bc;
    }
}

// ---------------- launch ----------------
extern "C" void kernel_launch(void* const* d_in, const int* in_sizes, int n_in,
                              void* d_out, int out_size) {
    (void)in_sizes; (void)n_in; (void)out_size;
    const float* enc   = (const float*)d_in[0];
    const float* W1    = (const float*)d_in[1];
    const float* b1    = (const float*)d_in[2];
    const float* W2    = (const float*)d_in[3];
    const float* b2    = (const float*)d_in[4];
    const float* Winv  = (const float*)d_in[5];
    const float* binv  = (const float*)d_in[6];
    const float* Wconv = (const float*)d_in[7];
    const float* bconv = (const float*)d_in[8];
    float* out = (float*)d_out;

    cudaFuncSetAttribute(decoder_main, cudaFuncAttributeMaxDynamicSharedMemorySize,
                         SMEM_BYTES);

    prep_w1p<<<128, 256>>>(W1);
    prep_w2<<<64, 256>>>(W2, Winv, b2, binv);
    prep_w2p<<<64, 256>>>();
    decoder_main<<<NB, 256, SMEM_BYTES>>>(enc, b1, Wconv, bconv, out);
}